// round 1
// baseline (speedup 1.0000x reference)
#include <cuda_runtime.h>
#include <math.h>

#define S_LEN   2048
#define BATCH   2
#define D_MODEL 2048
#define KV_DIM  512
#define NH      32
#define NKV     8
#define HD      64
#define ROWS    (BATCH*S_LEN)   // 4096

// Scratch (device globals — no allocation allowed)
__device__ float g_Q[ROWS*D_MODEL];
__device__ float g_K[ROWS*KV_DIM];
__device__ float g_V[ROWS*KV_DIM];
__device__ float g_O[ROWS*D_MODEL];

// ---------------------------------------------------------------------------
// Classic 128x128x8 SGEMM, 256 threads, 8x8 per-thread microtile.
// C[M,N] = A[M,K] @ B[K,N], all row-major fp32.
// ---------------------------------------------------------------------------
__global__ __launch_bounds__(256) void sgemm128(
    const float* __restrict__ A, const float* __restrict__ B,
    float* __restrict__ C, int M, int N, int K)
{
    __shared__ float As[8][128];
    __shared__ float Bs[8][128];
    const int tid = threadIdx.x;
    const int bx = blockIdx.x, by = blockIdx.y;
    const int tx = tid & 15, ty = tid >> 4;
    const int aRow = tid >> 1;
    const int aCol = (tid & 1) * 4;
    const int bRow = tid >> 5;
    const int bCol = (tid & 31) * 4;

    const float* Ab = A + (size_t)(by * 128) * K;
    const float* Bb = B + bx * 128;

    float acc[8][8];
    #pragma unroll
    for (int i = 0; i < 8; i++)
        #pragma unroll
        for (int j = 0; j < 8; j++) acc[i][j] = 0.f;

    for (int k0 = 0; k0 < K; k0 += 8) {
        float4 av = *(const float4*)(Ab + (size_t)aRow * K + k0 + aCol);
        As[aCol + 0][aRow] = av.x;
        As[aCol + 1][aRow] = av.y;
        As[aCol + 2][aRow] = av.z;
        As[aCol + 3][aRow] = av.w;
        *(float4*)(&Bs[bRow][bCol]) =
            *(const float4*)(Bb + (size_t)(k0 + bRow) * N + bCol);
        __syncthreads();

        #pragma unroll
        for (int kk = 0; kk < 8; kk++) {
            float4 a0 = *(const float4*)(&As[kk][ty * 8]);
            float4 a1 = *(const float4*)(&As[kk][ty * 8 + 4]);
            float4 b0 = *(const float4*)(&Bs[kk][tx * 8]);
            float4 b1 = *(const float4*)(&Bs[kk][tx * 8 + 4]);
            float ar[8] = {a0.x, a0.y, a0.z, a0.w, a1.x, a1.y, a1.z, a1.w};
            float br[8] = {b0.x, b0.y, b0.z, b0.w, b1.x, b1.y, b1.z, b1.w};
            #pragma unroll
            for (int i = 0; i < 8; i++)
                #pragma unroll
                for (int j = 0; j < 8; j++)
                    acc[i][j] = fmaf(ar[i], br[j], acc[i][j]);
        }
        __syncthreads();
    }

    float* Cb = C + (size_t)(by * 128 + ty * 8) * N + bx * 128 + tx * 8;
    #pragma unroll
    for (int i = 0; i < 8; i++) {
        *(float4*)(Cb + (size_t)i * N)     = make_float4(acc[i][0], acc[i][1], acc[i][2], acc[i][3]);
        *(float4*)(Cb + (size_t)i * N + 4) = make_float4(acc[i][4], acc[i][5], acc[i][6], acc[i][7]);
    }
}

// ---------------------------------------------------------------------------
// RoPE in-place on g_Q and g_K. Freq table computed on host (fp64, correctly
// rounded to fp32) and passed by value; angle = float(s) * freq matches the
// reference's fp32 computation.
// ---------------------------------------------------------------------------
struct Freqs { float f[32]; };

__global__ void rope_kernel(Freqs fr)
{
    int idx = blockIdx.x * blockDim.x + threadIdx.x;
    const int QP = ROWS * NH * (HD / 2);   // 4,194,304
    const int KP = ROWS * NKV * (HD / 2);  // 1,048,576
    float2* ptr;
    int s, p;
    if (idx < QP) {
        int row = idx >> 10;            // 1024 pairs per Q row
        int pr  = idx & 1023;
        p = pr & 31;
        int h = pr >> 5;
        s = row & (S_LEN - 1);
        ptr = (float2*)(g_Q + (size_t)row * D_MODEL + h * HD) + p;
    } else if (idx < QP + KP) {
        int j = idx - QP;
        int row = j >> 8;               // 256 pairs per K row
        int pr  = j & 255;
        p = pr & 31;
        int h = pr >> 5;
        s = row & (S_LEN - 1);
        ptr = (float2*)(g_K + (size_t)row * KV_DIM + h * HD) + p;
    } else {
        return;
    }
    float ang = (float)s * fr.f[p];
    float c, sn;
    sincosf(ang, &sn, &c);
    float2 v = *ptr;
    *ptr = make_float2(v.x * c - v.y * sn, v.x * sn + v.y * c);
}

// ---------------------------------------------------------------------------
// Flash attention, fp32. 64x64 Q/K tiles, 256 threads, 4x4 microtiles.
// Dynamic smem: Qs[64][65], KPs[64][65] (K tile reused as P tile), Vt[64][65]
// (V transposed), + alpha/l arrays.
// ---------------------------------------------------------------------------
__global__ __launch_bounds__(256) void flash_kernel()
{
    extern __shared__ float sm[];
    float (*Qs)[65]  = (float(*)[65])sm;
    float (*KPs)[65] = (float(*)[65])(sm + 64 * 65);
    float (*Vt)[65]  = (float(*)[65])(sm + 2 * 64 * 65);
    float* sAlpha = sm + 3 * 64 * 65;
    float* sL     = sAlpha + 64;

    const int qb = gridDim.x - 1 - blockIdx.x;  // heavy blocks first
    const int h  = blockIdx.y;
    const int b  = blockIdx.z;
    const int kvh = h >> 2;                      // GQA: repeat factor 4
    const int tid = threadIdx.x;
    const int tr = tid >> 4, tc = tid & 15;
    const int r0 = tr * 4, c0 = tc * 4;

    const float* Qb = g_Q + ((size_t)(b * S_LEN + qb * 64)) * D_MODEL + h * HD;
    #pragma unroll
    for (int e = 0; e < 16; e++) {
        int lin = tid + e * 256;
        int r = lin >> 6, d = lin & 63;
        Qs[r][d] = Qb[(size_t)r * D_MODEL + d];
    }

    float m_i = -1e30f, l_i = 0.f;
    float o[4][4] = {};

    for (int kb = 0; kb <= qb; kb++) {
        const float* Kb = g_K + ((size_t)(b * S_LEN + kb * 64)) * KV_DIM + kvh * HD;
        const float* Vb = g_V + ((size_t)(b * S_LEN + kb * 64)) * KV_DIM + kvh * HD;
        __syncthreads();  // previous-iter P/V reads done (also covers Q load on iter 0)
        #pragma unroll
        for (int e = 0; e < 16; e++) {
            int lin = tid + e * 256;
            int r = lin >> 6, d = lin & 63;
            KPs[r][d] = Kb[(size_t)r * KV_DIM + d];
            Vt[d][r]  = Vb[(size_t)r * KV_DIM + d];
        }
        __syncthreads();

        // S = Q K^T (4x4 per thread)
        float acc[4][4] = {};
        #pragma unroll 8
        for (int d = 0; d < 64; d++) {
            float qv[4], kv[4];
            #pragma unroll
            for (int i = 0; i < 4; i++) qv[i] = Qs[r0 + i][d];
            #pragma unroll
            for (int j = 0; j < 4; j++) kv[j] = KPs[c0 + j][d];
            #pragma unroll
            for (int i = 0; i < 4; i++)
                #pragma unroll
                for (int j = 0; j < 4; j++)
                    acc[i][j] = fmaf(qv[i], kv[j], acc[i][j]);
        }
        __syncthreads();  // all K reads done before overwriting KPs with scores

        const bool diag = (kb == qb);
        #pragma unroll
        for (int i = 0; i < 4; i++)
            #pragma unroll
            for (int j = 0; j < 4; j++) {
                float v = acc[i][j] * 0.125f;  // 1/sqrt(64)
                if (diag && (c0 + j > r0 + i)) v = -1e30f;
                KPs[r0 + i][c0 + j] = v;
            }
        __syncthreads();

        // Streaming softmax: one thread per row
        if (tid < 64) {
            float mx = m_i;
            #pragma unroll 8
            for (int j = 0; j < 64; j++) mx = fmaxf(mx, KPs[tid][j]);
            float alpha = expf(m_i - mx);
            float sum = 0.f;
            #pragma unroll 8
            for (int j = 0; j < 64; j++) {
                float p = expf(KPs[tid][j] - mx);
                KPs[tid][j] = p;
                sum += p;
            }
            l_i = l_i * alpha + sum;
            m_i = mx;
            sAlpha[tid] = alpha;
        }
        __syncthreads();

        // O = O*alpha + P V
        float al[4];
        #pragma unroll
        for (int i = 0; i < 4; i++) al[i] = sAlpha[r0 + i];
        #pragma unroll
        for (int i = 0; i < 4; i++)
            #pragma unroll
            for (int j = 0; j < 4; j++) o[i][j] *= al[i];
        #pragma unroll 8
        for (int k = 0; k < 64; k++) {
            float pv[4], vv[4];
            #pragma unroll
            for (int i = 0; i < 4; i++) pv[i] = KPs[r0 + i][k];
            #pragma unroll
            for (int j = 0; j < 4; j++) vv[j] = Vt[c0 + j][k];
            #pragma unroll
            for (int i = 0; i < 4; i++)
                #pragma unroll
                for (int j = 0; j < 4; j++)
                    o[i][j] = fmaf(pv[i], vv[j], o[i][j]);
        }
    }

    if (tid < 64) sL[tid] = l_i;
    __syncthreads();

    float* Ob = g_O + ((size_t)(b * S_LEN + qb * 64)) * D_MODEL + h * HD;
    #pragma unroll
    for (int i = 0; i < 4; i++) {
        float inv = 1.f / sL[r0 + i];
        #pragma unroll
        for (int j = 0; j < 4; j++)
            Ob[(size_t)(r0 + i) * D_MODEL + c0 + j] = o[i][j] * inv;
    }
}

// ---------------------------------------------------------------------------
// Launch: QKV GEMMs -> RoPE -> flash attention -> output GEMM
// Inputs (metadata order): x, mask(unused), wq, wk, wv, wo
// ---------------------------------------------------------------------------
extern "C" void kernel_launch(void* const* d_in, const int* in_sizes, int n_in,
                              void* d_out, int out_size)
{
    const float* x  = (const float*)d_in[0];
    const float* wq = (const float*)d_in[2];
    const float* wk = (const float*)d_in[3];
    const float* wv = (const float*)d_in[4];
    const float* wo = (const float*)d_in[5];
    float* out = (float*)d_out;

    float *qp, *kp, *vp, *op;
    cudaGetSymbolAddress((void**)&qp, g_Q);
    cudaGetSymbolAddress((void**)&kp, g_K);
    cudaGetSymbolAddress((void**)&vp, g_V);
    cudaGetSymbolAddress((void**)&op, g_O);

    // QKV projections
    sgemm128<<<dim3(D_MODEL / 128, ROWS / 128), 256>>>(x, wq, qp, ROWS, D_MODEL, D_MODEL);
    sgemm128<<<dim3(KV_DIM / 128, ROWS / 128), 256>>>(x, wk, kp, ROWS, KV_DIM, D_MODEL);
    sgemm128<<<dim3(KV_DIM / 128, ROWS / 128), 256>>>(x, wv, vp, ROWS, KV_DIM, D_MODEL);

    // RoPE (freqs computed in fp64 on host, correctly rounded to fp32)
    Freqs fr;
    for (int p = 0; p < 32; p++)
        fr.f[p] = (float)pow(10000.0, -(double)(2 * p) / 64.0);
    int total_pairs = ROWS * (NH + NKV) * (HD / 2);
    rope_kernel<<<(total_pairs + 255) / 256, 256>>>(fr);

    // Flash attention
    size_t shm = (3 * 64 * 65 + 128) * sizeof(float);  // 50,432 B
    cudaFuncSetAttribute(flash_kernel, cudaFuncAttributeMaxDynamicSharedMemorySize, (int)shm);
    flash_kernel<<<dim3(S_LEN / 64, NH, BATCH), 256, shm>>>();

    // Output projection
    sgemm128<<<dim3(D_MODEL / 128, ROWS / 128), 256>>>(op, wo, out, ROWS, D_MODEL, D_MODEL);
}

// round 3
// speedup vs baseline: 1.8476x; 1.8476x over previous
#include <cuda_runtime.h>
#include <cuda_bf16.h>
#include <math.h>
#include <stdint.h>

#define S_LEN   2048
#define BATCH   2
#define D_MODEL 2048
#define KV_DIM  512
#define NH      32
#define NKV     8
#define HD      64
#define ROWS    (BATCH*S_LEN)   // 4096

// ---------------- scratch (device globals; no allocation allowed) ----------
__device__ float g_Q[ROWS*D_MODEL];
__device__ float g_K[ROWS*KV_DIM];
__device__ float g_V[ROWS*KV_DIM];
__device__ float g_O[ROWS*D_MODEL];
__device__ __nv_bfloat16 g_xh[ROWS*D_MODEL];        // A hi (x, later O)
__device__ __nv_bfloat16 g_xl[ROWS*D_MODEL];        // A lo
__device__ __nv_bfloat16 g_wh[D_MODEL*D_MODEL];     // W^T hi [N,K]
__device__ __nv_bfloat16 g_wl[D_MODEL*D_MODEL];     // W^T lo [N,K]

// ======================= base-ISA PTX helpers ===============================
__device__ __forceinline__ uint32_t smem_u32(const void* p) {
    uint32_t a;
    asm("{ .reg .u64 t; cvta.to.shared.u64 t, %1; cvt.u32.u64 %0, t; }"
        : "=r"(a) : "l"(p));
    return a;
}
__device__ __forceinline__ void cpa16(uint32_t saddr, const void* g) {
    asm volatile("cp.async.cg.shared.global [%0], [%1], 16;" :: "r"(saddr), "l"(g));
}
#define CP_COMMIT() asm volatile("cp.async.commit_group;" ::: "memory")
#define CP_WAIT(n)  asm volatile("cp.async.wait_group %0;" :: "n"(n) : "memory")

#define LDSM_X4(r0, r1, r2, r3, a) \
    asm volatile("ldmatrix.sync.aligned.m8n8.x4.shared.b16 {%0,%1,%2,%3}, [%4];" \
        : "=r"(r0), "=r"(r1), "=r"(r2), "=r"(r3) : "r"(a))

#define MMA_BF16(d, a, b0, b1) \
    asm volatile("mma.sync.aligned.m16n8k16.row.col.f32.bf16.bf16.f32 " \
        "{%0,%1,%2,%3}, {%4,%5,%6,%7}, {%8,%9}, {%0,%1,%2,%3};" \
        : "+f"((d)[0]), "+f"((d)[1]), "+f"((d)[2]), "+f"((d)[3]) \
        : "r"((a)[0]), "r"((a)[1]), "r"((a)[2]), "r"((a)[3]), "r"(b0), "r"(b1))

// ======================= split / transpose conversions ======================
__global__ void split_kernel(const float* __restrict__ a,
                             __nv_bfloat16* __restrict__ hi,
                             __nv_bfloat16* __restrict__ lo, int n4)
{
    int i = blockIdx.x * blockDim.x + threadIdx.x;
    if (i >= n4) return;
    float4 v = ((const float4*)a)[i];
    __nv_bfloat16 h0 = __float2bfloat16(v.x), h1 = __float2bfloat16(v.y);
    __nv_bfloat16 h2 = __float2bfloat16(v.z), h3 = __float2bfloat16(v.w);
    __nv_bfloat16 l0 = __float2bfloat16(v.x - __bfloat162float(h0));
    __nv_bfloat16 l1 = __float2bfloat16(v.y - __bfloat162float(h1));
    __nv_bfloat16 l2 = __float2bfloat16(v.z - __bfloat162float(h2));
    __nv_bfloat16 l3 = __float2bfloat16(v.w - __bfloat162float(h3));
    ((__nv_bfloat162*)hi)[2*i]   = __nv_bfloat162(h0, h1);
    ((__nv_bfloat162*)hi)[2*i+1] = __nv_bfloat162(h2, h3);
    ((__nv_bfloat162*)lo)[2*i]   = __nv_bfloat162(l0, l1);
    ((__nv_bfloat162*)lo)[2*i+1] = __nv_bfloat162(l2, l3);
}

// W[K,N] fp32 -> Wt_hi[N,K], Wt_lo[N,K] bf16
__global__ void splitT_kernel(const float* __restrict__ w,
                              __nv_bfloat16* __restrict__ th,
                              __nv_bfloat16* __restrict__ tl, int Kd, int Nd)
{
    __shared__ float t[32][33];
    int n0 = blockIdx.x * 32, k0 = blockIdx.y * 32;
    for (int r = threadIdx.y; r < 32; r += 8)
        t[r][threadIdx.x] = w[(size_t)(k0 + r) * Nd + n0 + threadIdx.x];
    __syncthreads();
    for (int r = threadIdx.y; r < 32; r += 8) {
        float v = t[threadIdx.x][r];
        __nv_bfloat16 h = __float2bfloat16(v);
        __nv_bfloat16 l = __float2bfloat16(v - __bfloat162float(h));
        th[(size_t)(n0 + r) * Kd + k0 + threadIdx.x] = h;
        tl[(size_t)(n0 + r) * Kd + k0 + threadIdx.x] = l;
    }
}

// ======================= mma.sync bf16x3 GEMM ===============================
// C[M,N] = (Ah+Al)[M,K] @ (Bh+Bl)[N,K]^T, fp32 reg accumulate.
// 128x128 CTA tile, 8 warps (2m x 4n) of 64x32, BK=32, 4-stage cp.async.
#define BM 128
#define BN 128
#define BK 32
#define STAGES 4
#define TILE_B  (BM*BK*2)        // 8192 B per operand tile
#define STAGE_B (4*TILE_B)       // 32768 B

__global__ __launch_bounds__(256, 1) void gemm_mma(
    const __nv_bfloat16* __restrict__ Ah, const __nv_bfloat16* __restrict__ Al,
    const __nv_bfloat16* __restrict__ Bh, const __nv_bfloat16* __restrict__ Bl,
    float* __restrict__ C, int M, int N, int K)
{
    extern __shared__ char smem_raw[];
    const int tid  = threadIdx.x;
    const int wid  = tid >> 5;
    const int lane = tid & 31;
    const int m0 = blockIdx.y * BM, n0 = blockIdx.x * BN;
    const int wm = (wid >> 2) * 64;      // warp m offset: 0 / 64
    const int wn = (wid & 3) * 32;       // warp n offset: 0..96
    const int nk = K / BK;

    uint32_t raw = smem_u32(smem_raw);
    uint32_t st  = (raw + 1023u) & ~1023u;  // 1024-aligned tile region

    const __nv_bfloat16* gA_h = Ah + (size_t)m0 * K;
    const __nv_bfloat16* gA_l = Al + (size_t)m0 * K;
    const __nv_bfloat16* gB_h = Bh + (size_t)n0 * K;
    const __nv_bfloat16* gB_l = Bl + (size_t)n0 * K;

    // each thread: 2 chunks of 16B per 8KB tile
    const int ci0 = tid, ci1 = tid + 256;
    const int r0c = ci0 >> 2, c0c = ci0 & 3;
    const int r1c = ci1 >> 2, c1c = ci1 & 3;
    const uint32_t so0 = r0c * 64 + ((c0c ^ ((r0c >> 1) & 3)) << 4);
    const uint32_t so1 = r1c * 64 + ((c1c ^ ((r1c >> 1) & 3)) << 4);
    const size_t go0 = (size_t)r0c * K + c0c * 8;
    const size_t go1 = (size_t)r1c * K + c1c * 8;

    auto load_stage = [&](int s, int j) {
        uint32_t sb = st + s * STAGE_B;
        size_t kk = (size_t)j * BK;
        cpa16(sb + so0,              gA_h + kk + go0);
        cpa16(sb + so1,              gA_h + kk + go1);
        cpa16(sb + TILE_B + so0,     gA_l + kk + go0);
        cpa16(sb + TILE_B + so1,     gA_l + kk + go1);
        cpa16(sb + 2*TILE_B + so0,   gB_h + kk + go0);
        cpa16(sb + 2*TILE_B + so1,   gB_h + kk + go1);
        cpa16(sb + 3*TILE_B + so0,   gB_l + kk + go0);
        cpa16(sb + 3*TILE_B + so1,   gB_l + kk + go1);
    };

    float acc[4][4][4];
    #pragma unroll
    for (int i = 0; i < 4; i++)
        #pragma unroll
        for (int j = 0; j < 4; j++)
            #pragma unroll
            for (int k = 0; k < 4; k++) acc[i][j][k] = 0.f;

    // ldmatrix per-lane address components
    const int arow = wm + (lane & 15);          // + mt*16
    const int acol = (lane >> 4);               // + 2*ks
    const int brow = wn + (lane & 7) + ((lane >> 4) & 1) * 8;   // + nt*16
    const int bcol = (lane >> 3) & 1;           // + 2*ks

    // ---- pipeline ----
    #pragma unroll
    for (int s = 0; s < STAGES - 1; s++) {
        if (s < nk) load_stage(s, s);
        CP_COMMIT();
    }

    for (int i = 0; i < nk; i++) {
        int pf = i + STAGES - 1;
        if (pf < nk) load_stage(pf % STAGES, pf);
        CP_COMMIT();
        CP_WAIT(STAGES - 2);
        __syncthreads();

        uint32_t sb = st + (i % STAGES) * STAGE_B;
        #pragma unroll
        for (int ks = 0; ks < 2; ks++) {
            uint32_t ah[4][4], al[4][4], bh[2][4], bl[2][4];
            int ca = 2 * ks + acol;
            #pragma unroll
            for (int mt = 0; mt < 4; mt++) {
                int row = arow + mt * 16;
                uint32_t ad = sb + row * 64 + ((ca ^ ((row >> 1) & 3)) << 4);
                LDSM_X4(ah[mt][0], ah[mt][1], ah[mt][2], ah[mt][3], ad);
                LDSM_X4(al[mt][0], al[mt][1], al[mt][2], al[mt][3], ad + TILE_B);
            }
            int cb = 2 * ks + bcol;
            #pragma unroll
            for (int nt = 0; nt < 2; nt++) {
                int row = brow + nt * 16;
                uint32_t bd = sb + 2*TILE_B + row * 64 + ((cb ^ ((row >> 1) & 3)) << 4);
                LDSM_X4(bh[nt][0], bh[nt][1], bh[nt][2], bh[nt][3], bd);
                LDSM_X4(bl[nt][0], bl[nt][1], bl[nt][2], bl[nt][3], bd + TILE_B);
            }
            #pragma unroll
            for (int mt = 0; mt < 4; mt++)
                #pragma unroll
                for (int nti = 0; nti < 4; nti++) {
                    uint32_t b0h = bh[nti >> 1][(nti & 1) * 2];
                    uint32_t b1h = bh[nti >> 1][(nti & 1) * 2 + 1];
                    uint32_t b0l = bl[nti >> 1][(nti & 1) * 2];
                    uint32_t b1l = bl[nti >> 1][(nti & 1) * 2 + 1];
                    MMA_BF16(acc[mt][nti], ah[mt], b0h, b1h);   // hi*hi
                    MMA_BF16(acc[mt][nti], ah[mt], b0l, b1l);   // hi*lo
                    MMA_BF16(acc[mt][nti], al[mt], b0h, b1h);   // lo*hi
                }
        }
        __syncthreads();
    }

    // ---- epilogue ----
    #pragma unroll
    for (int mt = 0; mt < 4; mt++)
        #pragma unroll
        for (int nti = 0; nti < 4; nti++) {
            int gm = m0 + wm + mt * 16 + (lane >> 2);
            int gn = n0 + wn + nti * 8 + (lane & 3) * 2;
            *(float2*)&C[(size_t)gm * N + gn] =
                make_float2(acc[mt][nti][0], acc[mt][nti][1]);
            *(float2*)&C[(size_t)(gm + 8) * N + gn] =
                make_float2(acc[mt][nti][2], acc[mt][nti][3]);
        }
}

// ======================= RoPE ===============================================
struct Freqs { float f[32]; };

__global__ void rope_kernel(Freqs fr)
{
    int idx = blockIdx.x * blockDim.x + threadIdx.x;
    const int QP = ROWS * NH * (HD / 2);
    const int KP = ROWS * NKV * (HD / 2);
    float2* ptr;
    int s, p;
    if (idx < QP) {
        int row = idx >> 10;
        int pr  = idx & 1023;
        p = pr & 31;
        int h = pr >> 5;
        s = row & (S_LEN - 1);
        ptr = (float2*)(g_Q + (size_t)row * D_MODEL + h * HD) + p;
    } else if (idx < QP + KP) {
        int j = idx - QP;
        int row = j >> 8;
        int pr  = j & 255;
        p = pr & 31;
        int h = pr >> 5;
        s = row & (S_LEN - 1);
        ptr = (float2*)(g_K + (size_t)row * KV_DIM + h * HD) + p;
    } else return;
    float ang = (float)s * fr.f[p];
    float c, sn;
    sincosf(ang, &sn, &c);
    float2 v = *ptr;
    *ptr = make_float2(v.x * c - v.y * sn, v.x * sn + v.y * c);
}

// ======================= Flash attention (fp32, unchanged) ==================
__global__ __launch_bounds__(256) void flash_kernel()
{
    extern __shared__ float sm[];
    float (*Qs)[65]  = (float(*)[65])sm;
    float (*KPs)[65] = (float(*)[65])(sm + 64 * 65);
    float (*Vt)[65]  = (float(*)[65])(sm + 2 * 64 * 65);
    float* sAlpha = sm + 3 * 64 * 65;
    float* sL     = sAlpha + 64;

    const int qb = gridDim.x - 1 - blockIdx.x;
    const int h  = blockIdx.y;
    const int b  = blockIdx.z;
    const int kvh = h >> 2;
    const int tid = threadIdx.x;
    const int tr = tid >> 4, tc = tid & 15;
    const int r0 = tr * 4, c0 = tc * 4;

    const float* Qb = g_Q + ((size_t)(b * S_LEN + qb * 64)) * D_MODEL + h * HD;
    #pragma unroll
    for (int e = 0; e < 16; e++) {
        int lin = tid + e * 256;
        int r = lin >> 6, d = lin & 63;
        Qs[r][d] = Qb[(size_t)r * D_MODEL + d];
    }

    float m_i = -1e30f, l_i = 0.f;
    float o[4][4] = {};

    for (int kb = 0; kb <= qb; kb++) {
        const float* Kb = g_K + ((size_t)(b * S_LEN + kb * 64)) * KV_DIM + kvh * HD;
        const float* Vb = g_V + ((size_t)(b * S_LEN + kb * 64)) * KV_DIM + kvh * HD;
        __syncthreads();
        #pragma unroll
        for (int e = 0; e < 16; e++) {
            int lin = tid + e * 256;
            int r = lin >> 6, d = lin & 63;
            KPs[r][d] = Kb[(size_t)r * KV_DIM + d];
            Vt[d][r]  = Vb[(size_t)r * KV_DIM + d];
        }
        __syncthreads();

        float acc[4][4] = {};
        #pragma unroll 8
        for (int d = 0; d < 64; d++) {
            float qv[4], kv[4];
            #pragma unroll
            for (int i = 0; i < 4; i++) qv[i] = Qs[r0 + i][d];
            #pragma unroll
            for (int j = 0; j < 4; j++) kv[j] = KPs[c0 + j][d];
            #pragma unroll
            for (int i = 0; i < 4; i++)
                #pragma unroll
                for (int j = 0; j < 4; j++)
                    acc[i][j] = fmaf(qv[i], kv[j], acc[i][j]);
        }
        __syncthreads();

        const bool diag = (kb == qb);
        #pragma unroll
        for (int i = 0; i < 4; i++)
            #pragma unroll
            for (int j = 0; j < 4; j++) {
                float v = acc[i][j] * 0.125f;
                if (diag && (c0 + j > r0 + i)) v = -1e30f;
                KPs[r0 + i][c0 + j] = v;
            }
        __syncthreads();

        if (tid < 64) {
            float mx = m_i;
            #pragma unroll 8
            for (int j = 0; j < 64; j++) mx = fmaxf(mx, KPs[tid][j]);
            float alpha = expf(m_i - mx);
            float sum = 0.f;
            #pragma unroll 8
            for (int j = 0; j < 64; j++) {
                float p = expf(KPs[tid][j] - mx);
                KPs[tid][j] = p;
                sum += p;
            }
            l_i = l_i * alpha + sum;
            m_i = mx;
            sAlpha[tid] = alpha;
        }
        __syncthreads();

        float al[4];
        #pragma unroll
        for (int i = 0; i < 4; i++) al[i] = sAlpha[r0 + i];
        #pragma unroll
        for (int i = 0; i < 4; i++)
            #pragma unroll
            for (int j = 0; j < 4; j++) o[i][j] *= al[i];
        #pragma unroll 8
        for (int k = 0; k < 64; k++) {
            float pv[4], vv[4];
            #pragma unroll
            for (int i = 0; i < 4; i++) pv[i] = KPs[r0 + i][k];
            #pragma unroll
            for (int j = 0; j < 4; j++) vv[j] = Vt[c0 + j][k];
            #pragma unroll
            for (int i = 0; i < 4; i++)
                #pragma unroll
                for (int j = 0; j < 4; j++)
                    o[i][j] = fmaf(pv[i], vv[j], o[i][j]);
        }
    }

    if (tid < 64) sL[tid] = l_i;
    __syncthreads();

    float* Ob = g_O + ((size_t)(b * S_LEN + qb * 64)) * D_MODEL + h * HD;
    #pragma unroll
    for (int i = 0; i < 4; i++) {
        float inv = 1.f / sL[r0 + i];
        #pragma unroll
        for (int j = 0; j < 4; j++)
            Ob[(size_t)(r0 + i) * D_MODEL + c0 + j] = o[i][j] * inv;
    }
}

// ======================= host launch =========================================
static void launch_gemm(const __nv_bfloat16* Ah, const __nv_bfloat16* Al,
                        const __nv_bfloat16* Bh, const __nv_bfloat16* Bl,
                        float* C, int M, int N, int K)
{
    size_t shm = STAGES * STAGE_B + 1024;
    cudaFuncSetAttribute(gemm_mma, cudaFuncAttributeMaxDynamicSharedMemorySize, (int)shm);
    gemm_mma<<<dim3(N / BN, M / BM), 256, shm>>>(Ah, Al, Bh, Bl, C, M, N, K);
}

extern "C" void kernel_launch(void* const* d_in, const int* in_sizes, int n_in,
                              void* d_out, int out_size)
{
    const float* x  = (const float*)d_in[0];
    const float* wq = (const float*)d_in[2];
    const float* wk = (const float*)d_in[3];
    const float* wv = (const float*)d_in[4];
    const float* wo = (const float*)d_in[5];
    float* out = (float*)d_out;

    float *qp, *kp, *vp, *op;
    __nv_bfloat16 *xh, *xl, *wh, *wl;
    cudaGetSymbolAddress((void**)&qp, g_Q);
    cudaGetSymbolAddress((void**)&kp, g_K);
    cudaGetSymbolAddress((void**)&vp, g_V);
    cudaGetSymbolAddress((void**)&op, g_O);
    cudaGetSymbolAddress((void**)&xh, g_xh);
    cudaGetSymbolAddress((void**)&xl, g_xl);
    cudaGetSymbolAddress((void**)&wh, g_wh);
    cudaGetSymbolAddress((void**)&wl, g_wl);

    // split x -> bf16 hi/lo
    int n4 = ROWS * D_MODEL / 4;
    split_kernel<<<(n4 + 255) / 256, 256>>>(x, xh, xl, n4);

    // Q = x @ wq
    splitT_kernel<<<dim3(D_MODEL / 32, D_MODEL / 32), dim3(32, 8)>>>(wq, wh, wl, D_MODEL, D_MODEL);
    launch_gemm(xh, xl, wh, wl, qp, ROWS, D_MODEL, D_MODEL);
    // K = x @ wk
    splitT_kernel<<<dim3(KV_DIM / 32, D_MODEL / 32), dim3(32, 8)>>>(wk, wh, wl, D_MODEL, KV_DIM);
    launch_gemm(xh, xl, wh, wl, kp, ROWS, KV_DIM, D_MODEL);
    // V = x @ wv
    splitT_kernel<<<dim3(KV_DIM / 32, D_MODEL / 32), dim3(32, 8)>>>(wv, wh, wl, D_MODEL, KV_DIM);
    launch_gemm(xh, xl, wh, wl, vp, ROWS, KV_DIM, D_MODEL);

    // RoPE
    Freqs fr;
    for (int p = 0; p < 32; p++)
        fr.f[p] = (float)pow(10000.0, -(double)(2 * p) / 64.0);
    int total_pairs = ROWS * (NH + NKV) * (HD / 2);
    rope_kernel<<<(total_pairs + 255) / 256, 256>>>(fr);

    // Flash attention
    size_t shm = (3 * 64 * 65 + 128) * sizeof(float);
    cudaFuncSetAttribute(flash_kernel, cudaFuncAttributeMaxDynamicSharedMemorySize, (int)shm);
    flash_kernel<<<dim3(S_LEN / 64, NH, BATCH), 256, shm>>>();

    // out = O @ wo  (reuse xh/xl for O's split)
    split_kernel<<<(n4 + 255) / 256, 256>>>(op, xh, xl, n4);
    splitT_kernel<<<dim3(D_MODEL / 32, D_MODEL / 32), dim3(32, 8)>>>(wo, wh, wl, D_MODEL, D_MODEL);
    launch_gemm(xh, xl, wh, wl, out, ROWS, D_MODEL, D_MODEL);
}

// round 4
// speedup vs baseline: 3.2587x; 1.7637x over previous
#include <cuda_runtime.h>
#include <cuda_bf16.h>
#include <math.h>
#include <stdint.h>

#define S_LEN   2048
#define BATCH   2
#define D_MODEL 2048
#define KV_DIM  512
#define NH      32
#define NKV     8
#define HD      64
#define ROWS    (BATCH*S_LEN)   // 4096

// ---------------- scratch (device globals; no allocation allowed) ----------
__device__ float g_Q[ROWS*D_MODEL];
__device__ float g_K[ROWS*KV_DIM];
__device__ float g_V[ROWS*KV_DIM];
__device__ float g_O[ROWS*D_MODEL];
__device__ __nv_bfloat16 g_xh[ROWS*D_MODEL];
__device__ __nv_bfloat16 g_xl[ROWS*D_MODEL];
__device__ __nv_bfloat16 g_wh[D_MODEL*D_MODEL];
__device__ __nv_bfloat16 g_wl[D_MODEL*D_MODEL];
// flash operands (bf16 hi/lo, RoPE applied, Q pre-scaled by 0.125)
__device__ __nv_bfloat16 g_Qh[ROWS*D_MODEL];
__device__ __nv_bfloat16 g_Ql[ROWS*D_MODEL];
__device__ __nv_bfloat16 g_Kh[ROWS*KV_DIM];
__device__ __nv_bfloat16 g_Kl[ROWS*KV_DIM];
__device__ __nv_bfloat16 g_Vth[BATCH*NKV*HD*S_LEN];   // [b][kvh][d][s]
__device__ __nv_bfloat16 g_Vtl[BATCH*NKV*HD*S_LEN];

// ======================= base-ISA PTX helpers ===============================
__device__ __forceinline__ uint32_t smem_u32(const void* p) {
    uint32_t a;
    asm("{ .reg .u64 t; cvta.to.shared.u64 t, %1; cvt.u32.u64 %0, t; }"
        : "=r"(a) : "l"(p));
    return a;
}
__device__ __forceinline__ void cpa16(uint32_t saddr, const void* g) {
    asm volatile("cp.async.cg.shared.global [%0], [%1], 16;" :: "r"(saddr), "l"(g));
}
#define CP_COMMIT() asm volatile("cp.async.commit_group;" ::: "memory")
#define CP_WAIT(n)  asm volatile("cp.async.wait_group %0;" :: "n"(n) : "memory")

#define LDSM_X4(r0, r1, r2, r3, a) \
    asm volatile("ldmatrix.sync.aligned.m8n8.x4.shared.b16 {%0,%1,%2,%3}, [%4];" \
        : "=r"(r0), "=r"(r1), "=r"(r2), "=r"(r3) : "r"(a))

#define MMA_BF16(d, a, b0, b1) \
    asm volatile("mma.sync.aligned.m16n8k16.row.col.f32.bf16.bf16.f32 " \
        "{%0,%1,%2,%3}, {%4,%5,%6,%7}, {%8,%9}, {%0,%1,%2,%3};" \
        : "+f"((d)[0]), "+f"((d)[1]), "+f"((d)[2]), "+f"((d)[3]) \
        : "r"((a)[0]), "r"((a)[1]), "r"((a)[2]), "r"((a)[3]), "r"(b0), "r"(b1))

// pack two fp32 -> bf16x2 (lo in lower half)
#define PACK_BF2(d, lo, hi) \
    asm("cvt.rn.bf16x2.f32 %0, %1, %2;" : "=r"(d) : "f"(hi), "f"(lo))

// ======================= split / transpose conversions ======================
__global__ void split_kernel(const float* __restrict__ a,
                             __nv_bfloat16* __restrict__ hi,
                             __nv_bfloat16* __restrict__ lo, int n4)
{
    int i = blockIdx.x * blockDim.x + threadIdx.x;
    if (i >= n4) return;
    float4 v = ((const float4*)a)[i];
    __nv_bfloat16 h0 = __float2bfloat16(v.x), h1 = __float2bfloat16(v.y);
    __nv_bfloat16 h2 = __float2bfloat16(v.z), h3 = __float2bfloat16(v.w);
    __nv_bfloat16 l0 = __float2bfloat16(v.x - __bfloat162float(h0));
    __nv_bfloat16 l1 = __float2bfloat16(v.y - __bfloat162float(h1));
    __nv_bfloat16 l2 = __float2bfloat16(v.z - __bfloat162float(h2));
    __nv_bfloat16 l3 = __float2bfloat16(v.w - __bfloat162float(h3));
    ((__nv_bfloat162*)hi)[2*i]   = __nv_bfloat162(h0, h1);
    ((__nv_bfloat162*)hi)[2*i+1] = __nv_bfloat162(h2, h3);
    ((__nv_bfloat162*)lo)[2*i]   = __nv_bfloat162(l0, l1);
    ((__nv_bfloat162*)lo)[2*i+1] = __nv_bfloat162(l2, l3);
}

__global__ void splitT_kernel(const float* __restrict__ w,
                              __nv_bfloat16* __restrict__ th,
                              __nv_bfloat16* __restrict__ tl, int Kd, int Nd)
{
    __shared__ float t[32][33];
    int n0 = blockIdx.x * 32, k0 = blockIdx.y * 32;
    for (int r = threadIdx.y; r < 32; r += 8)
        t[r][threadIdx.x] = w[(size_t)(k0 + r) * Nd + n0 + threadIdx.x];
    __syncthreads();
    for (int r = threadIdx.y; r < 32; r += 8) {
        float v = t[threadIdx.x][r];
        __nv_bfloat16 h = __float2bfloat16(v);
        __nv_bfloat16 l = __float2bfloat16(v - __bfloat162float(h));
        th[(size_t)(n0 + r) * Kd + k0 + threadIdx.x] = h;
        tl[(size_t)(n0 + r) * Kd + k0 + threadIdx.x] = l;
    }
}

// ======================= mma.sync bf16x3 GEMM (unchanged, proven) ===========
#define BM 128
#define BN 128
#define BK 32
#define STAGES 4
#define TILE_B  (BM*BK*2)
#define STAGE_B (4*TILE_B)

__global__ __launch_bounds__(256, 1) void gemm_mma(
    const __nv_bfloat16* __restrict__ Ah, const __nv_bfloat16* __restrict__ Al,
    const __nv_bfloat16* __restrict__ Bh, const __nv_bfloat16* __restrict__ Bl,
    float* __restrict__ C, int M, int N, int K)
{
    extern __shared__ char smem_raw[];
    const int tid  = threadIdx.x;
    const int wid  = tid >> 5;
    const int lane = tid & 31;
    const int m0 = blockIdx.y * BM, n0 = blockIdx.x * BN;
    const int wm = (wid >> 2) * 64;
    const int wn = (wid & 3) * 32;
    const int nk = K / BK;

    uint32_t raw = smem_u32(smem_raw);
    uint32_t st  = (raw + 1023u) & ~1023u;

    const __nv_bfloat16* gA_h = Ah + (size_t)m0 * K;
    const __nv_bfloat16* gA_l = Al + (size_t)m0 * K;
    const __nv_bfloat16* gB_h = Bh + (size_t)n0 * K;
    const __nv_bfloat16* gB_l = Bl + (size_t)n0 * K;

    const int ci0 = tid, ci1 = tid + 256;
    const int r0c = ci0 >> 2, c0c = ci0 & 3;
    const int r1c = ci1 >> 2, c1c = ci1 & 3;
    const uint32_t so0 = r0c * 64 + ((c0c ^ ((r0c >> 1) & 3)) << 4);
    const uint32_t so1 = r1c * 64 + ((c1c ^ ((r1c >> 1) & 3)) << 4);
    const size_t go0 = (size_t)r0c * K + c0c * 8;
    const size_t go1 = (size_t)r1c * K + c1c * 8;

    auto load_stage = [&](int s, int j) {
        uint32_t sb = st + s * STAGE_B;
        size_t kk = (size_t)j * BK;
        cpa16(sb + so0,              gA_h + kk + go0);
        cpa16(sb + so1,              gA_h + kk + go1);
        cpa16(sb + TILE_B + so0,     gA_l + kk + go0);
        cpa16(sb + TILE_B + so1,     gA_l + kk + go1);
        cpa16(sb + 2*TILE_B + so0,   gB_h + kk + go0);
        cpa16(sb + 2*TILE_B + so1,   gB_h + kk + go1);
        cpa16(sb + 3*TILE_B + so0,   gB_l + kk + go0);
        cpa16(sb + 3*TILE_B + so1,   gB_l + kk + go1);
    };

    float acc[4][4][4];
    #pragma unroll
    for (int i = 0; i < 4; i++)
        #pragma unroll
        for (int j = 0; j < 4; j++)
            #pragma unroll
            for (int k = 0; k < 4; k++) acc[i][j][k] = 0.f;

    const int arow = wm + (lane & 15);
    const int acol = (lane >> 4);
    const int brow = wn + (lane & 7) + ((lane >> 4) & 1) * 8;
    const int bcol = (lane >> 3) & 1;

    #pragma unroll
    for (int s = 0; s < STAGES - 1; s++) {
        if (s < nk) load_stage(s, s);
        CP_COMMIT();
    }

    for (int i = 0; i < nk; i++) {
        int pf = i + STAGES - 1;
        if (pf < nk) load_stage(pf % STAGES, pf);
        CP_COMMIT();
        CP_WAIT(STAGES - 2);
        __syncthreads();

        uint32_t sb = st + (i % STAGES) * STAGE_B;
        #pragma unroll
        for (int ks = 0; ks < 2; ks++) {
            uint32_t ah[4][4], al[4][4], bh[2][4], bl[2][4];
            int ca = 2 * ks + acol;
            #pragma unroll
            for (int mt = 0; mt < 4; mt++) {
                int row = arow + mt * 16;
                uint32_t ad = sb + row * 64 + ((ca ^ ((row >> 1) & 3)) << 4);
                LDSM_X4(ah[mt][0], ah[mt][1], ah[mt][2], ah[mt][3], ad);
                LDSM_X4(al[mt][0], al[mt][1], al[mt][2], al[mt][3], ad + TILE_B);
            }
            int cb = 2 * ks + bcol;
            #pragma unroll
            for (int nt = 0; nt < 2; nt++) {
                int row = brow + nt * 16;
                uint32_t bd = sb + 2*TILE_B + row * 64 + ((cb ^ ((row >> 1) & 3)) << 4);
                LDSM_X4(bh[nt][0], bh[nt][1], bh[nt][2], bh[nt][3], bd);
                LDSM_X4(bl[nt][0], bl[nt][1], bl[nt][2], bl[nt][3], bd + TILE_B);
            }
            #pragma unroll
            for (int mt = 0; mt < 4; mt++)
                #pragma unroll
                for (int nti = 0; nti < 4; nti++) {
                    uint32_t b0h = bh[nti >> 1][(nti & 1) * 2];
                    uint32_t b1h = bh[nti >> 1][(nti & 1) * 2 + 1];
                    uint32_t b0l = bl[nti >> 1][(nti & 1) * 2];
                    uint32_t b1l = bl[nti >> 1][(nti & 1) * 2 + 1];
                    MMA_BF16(acc[mt][nti], ah[mt], b0h, b1h);
                    MMA_BF16(acc[mt][nti], ah[mt], b0l, b1l);
                    MMA_BF16(acc[mt][nti], al[mt], b0h, b1h);
                }
        }
        __syncthreads();
    }

    #pragma unroll
    for (int mt = 0; mt < 4; mt++)
        #pragma unroll
        for (int nti = 0; nti < 4; nti++) {
            int gm = m0 + wm + mt * 16 + (lane >> 2);
            int gn = n0 + wn + nti * 8 + (lane & 3) * 2;
            *(float2*)&C[(size_t)gm * N + gn] =
                make_float2(acc[mt][nti][0], acc[mt][nti][1]);
            *(float2*)&C[(size_t)(gm + 8) * N + gn] =
                make_float2(acc[mt][nti][2], acc[mt][nti][3]);
        }
}

// ======================= RoPE + split precompute ============================
struct Freqs { float f[32]; };

__global__ void rope_split_q(Freqs fr)
{
    int idx = blockIdx.x * blockDim.x + threadIdx.x;   // ROWS*NH*32
    int row = idx >> 10;
    int rem = idx & 1023;
    int h = rem >> 5, p = rem & 31;
    int s = row & (S_LEN - 1);
    size_t off = (size_t)row * D_MODEL + h * HD + 2 * p;
    float2 v = *(const float2*)(g_Q + off);
    float ang = (float)s * fr.f[p];
    float c, sn;
    sincosf(ang, &sn, &c);
    float xr = (v.x * c - v.y * sn) * 0.125f;   // fold 1/sqrt(64)
    float xi = (v.x * sn + v.y * c) * 0.125f;
    __nv_bfloat16 hr = __float2bfloat16(xr), hi_ = __float2bfloat16(xi);
    __nv_bfloat16 lr = __float2bfloat16(xr - __bfloat162float(hr));
    __nv_bfloat16 li = __float2bfloat16(xi - __bfloat162float(hi_));
    *(__nv_bfloat162*)(g_Qh + off) = __nv_bfloat162(hr, hi_);
    *(__nv_bfloat162*)(g_Ql + off) = __nv_bfloat162(lr, li);
}

__global__ void rope_split_k(Freqs fr)
{
    int idx = blockIdx.x * blockDim.x + threadIdx.x;   // ROWS*NKV*32
    int row = idx >> 8;
    int rem = idx & 255;
    int kv = rem >> 5, p = rem & 31;
    int s = row & (S_LEN - 1);
    size_t off = (size_t)row * KV_DIM + kv * HD + 2 * p;
    float2 v = *(const float2*)(g_K + off);
    float ang = (float)s * fr.f[p];
    float c, sn;
    sincosf(ang, &sn, &c);
    float xr = v.x * c - v.y * sn;
    float xi = v.x * sn + v.y * c;
    __nv_bfloat16 hr = __float2bfloat16(xr), hi_ = __float2bfloat16(xi);
    __nv_bfloat16 lr = __float2bfloat16(xr - __bfloat162float(hr));
    __nv_bfloat16 li = __float2bfloat16(xi - __bfloat162float(hi_));
    *(__nv_bfloat162*)(g_Kh + off) = __nv_bfloat162(hr, hi_);
    *(__nv_bfloat162*)(g_Kl + off) = __nv_bfloat162(lr, li);
}

// V[b*S+s][kvh*64+d] fp32 -> Vt[(b*NKV+kvh)*64+d][s] bf16 hi/lo
__global__ void vsplit_t()
{
    __shared__ float t[32][33];
    int bz = blockIdx.z;                 // b*NKV + kvh
    int d0 = blockIdx.y * 32;
    int s0 = blockIdx.x * 32;
    int b = bz >> 3, kvh = bz & 7;
    int tx = threadIdx.x, ty = threadIdx.y;
    for (int i = 0; i < 4; i++) {
        int r = ty + i * 8;
        t[r][tx] = g_V[(size_t)(b * S_LEN + s0 + r) * KV_DIM + kvh * HD + d0 + tx];
    }
    __syncthreads();
    for (int i = 0; i < 4; i++) {
        int rr = ty + i * 8;
        float v = t[tx][rr];             // V[s0+tx][d0+rr]
        __nv_bfloat16 h = __float2bfloat16(v);
        __nv_bfloat16 l = __float2bfloat16(v - __bfloat162float(h));
        size_t o = (size_t)(bz * HD + d0 + rr) * S_LEN + s0 + tx;
        g_Vth[o] = h;
        g_Vtl[o] = l;
    }
}

// ======================= flash attention, mma.sync bf16x3 ===================
// CTA: 128 q-rows, 8 warps x 16 rows; K/V tiles 64, double-buffered cp.async.
#define SQH 0
#define SQL 16384
#define SST 32768
#define FSTG 32768   // Kh 0 | Kl 8K | Vh 16K | Vl 24K

__global__ __launch_bounds__(256, 1) void flash_mma()
{
    extern __shared__ char smem_raw[];
    uint32_t raw = smem_u32(smem_raw);
    uint32_t sb = (raw + 1023u) & ~1023u;

    const int tid = threadIdx.x, lane = tid & 31, w = tid >> 5;
    const int qt = gridDim.x - 1 - blockIdx.x;   // heavy tiles first
    const int h = blockIdx.y, b = blockIdx.z;
    const int kvh = h >> 2;
    const int wq0 = qt * 128 + w * 16;

    // ---- issue Q tile load (group 0) ----
    {
        const size_t qg = ((size_t)(b * S_LEN + qt * 128)) * D_MODEL + h * HD;
        #pragma unroll
        for (int it = 0; it < 4; it++) {
            int c = tid + it * 256;
            int r = c >> 3, ch = c & 7;
            uint32_t so = (uint32_t)(r * 128 + ((ch ^ (r & 7)) << 4));
            size_t go = qg + (size_t)r * D_MODEL + ch * 8;
            cpa16(sb + SQH + so, g_Qh + go);
            cpa16(sb + SQL + so, g_Ql + go);
        }
    }
    CP_COMMIT();

    const int ldr = tid >> 3, ldc = tid & 7;     // K/V tile: 2 chunk-rows/thread
    const uint32_t lso0 = (uint32_t)(ldr * 128 + ((ldc ^ (ldr & 7)) << 4));
    const uint32_t lso1 = (uint32_t)((ldr + 32) * 128 + ((ldc ^ ((ldr + 32) & 7)) << 4));

    auto load_kv = [&](int stage, int kb) {
        uint32_t ss = sb + SST + stage * FSTG;
        size_t kg = ((size_t)(b * S_LEN + kb * 64)) * KV_DIM + kvh * HD;
        size_t vg = ((size_t)((b * NKV + kvh) * HD)) * S_LEN + (size_t)kb * 64;
        size_t kg0 = kg + (size_t)ldr * KV_DIM + ldc * 8;
        size_t kg1 = kg + (size_t)(ldr + 32) * KV_DIM + ldc * 8;
        size_t vg0 = vg + (size_t)ldr * S_LEN + ldc * 8;
        size_t vg1 = vg + (size_t)(ldr + 32) * S_LEN + ldc * 8;
        cpa16(ss + lso0,         g_Kh + kg0);
        cpa16(ss + lso1,         g_Kh + kg1);
        cpa16(ss + 8192 + lso0,  g_Kl + kg0);
        cpa16(ss + 8192 + lso1,  g_Kl + kg1);
        cpa16(ss + 16384 + lso0, g_Vth + vg0);
        cpa16(ss + 16384 + lso1, g_Vth + vg1);
        cpa16(ss + 24576 + lso0, g_Vtl + vg0);
        cpa16(ss + 24576 + lso1, g_Vtl + vg1);
        CP_COMMIT();
    };

    load_kv(0, 0);                                // group 1
    CP_WAIT(1);                                   // Q ready
    __syncthreads();

    // ---- hoist Q fragments ----
    uint32_t qh[4][4], ql[4][4];
    {
        int row = w * 16 + (lane & 15);
        int rb = row * 128;
        #pragma unroll
        for (int kf = 0; kf < 4; kf++) {
            int ch = kf * 2 + (lane >> 4);
            uint32_t off = (uint32_t)(rb + ((ch ^ (row & 7)) << 4));
            LDSM_X4(qh[kf][0], qh[kf][1], qh[kf][2], qh[kf][3], sb + SQH + off);
            LDSM_X4(ql[kf][0], ql[kf][1], ql[kf][2], ql[kf][3], sb + SQL + off);
        }
    }

    float o[8][4];
    #pragma unroll
    for (int i = 0; i < 8; i++)
        #pragma unroll
        for (int j = 0; j < 4; j++) o[i][j] = 0.f;
    float m0 = -1e30f, m1 = -1e30f, l0 = 0.f, l1 = 0.f;

    const int brn = (lane & 7) + ((lane >> 4) & 1) * 8;
    const int bcc = (lane >> 3) & 1;
    const int nkb = 2 * qt + 2;

    for (int kb = 0; kb < nkb; kb++) {
        if (kb + 1 < nkb) {
            load_kv((kb + 1) & 1, kb + 1);
            CP_WAIT(1);
        } else {
            CP_WAIT(0);
        }
        __syncthreads();

        uint32_t ks = sb + SST + (kb & 1) * FSTG;

        // ---- S = Q K^T (bf16x3) ----
        float s[8][4];
        #pragma unroll
        for (int i = 0; i < 8; i++)
            #pragma unroll
            for (int j = 0; j < 4; j++) s[i][j] = 0.f;

        #pragma unroll
        for (int kf = 0; kf < 4; kf++) {
            uint32_t bh[4][4], bl[4][4];
            int ch = kf * 2 + bcc;
            #pragma unroll
            for (int np = 0; np < 4; np++) {
                int row = brn + np * 16;
                uint32_t off = (uint32_t)(row * 128 + ((ch ^ (row & 7)) << 4));
                LDSM_X4(bh[np][0], bh[np][1], bh[np][2], bh[np][3], ks + off);
                LDSM_X4(bl[np][0], bl[np][1], bl[np][2], bl[np][3], ks + 8192 + off);
            }
            #pragma unroll
            for (int nt = 0; nt < 8; nt++) {
                uint32_t b0h = bh[nt >> 1][(nt & 1) * 2];
                uint32_t b1h = bh[nt >> 1][(nt & 1) * 2 + 1];
                uint32_t b0l = bl[nt >> 1][(nt & 1) * 2];
                uint32_t b1l = bl[nt >> 1][(nt & 1) * 2 + 1];
                MMA_BF16(s[nt], qh[kf], b0h, b1h);
                MMA_BF16(s[nt], qh[kf], b0l, b1l);
                MMA_BF16(s[nt], ql[kf], b0h, b1h);
            }
        }

        // ---- causal mask ----
        int kbase = kb * 64;
        if (kbase + 63 > wq0) {
            int q0 = wq0 + (lane >> 2);
            int q1 = q0 + 8;
            #pragma unroll
            for (int nt = 0; nt < 8; nt++) {
                int k0 = kbase + nt * 8 + (lane & 3) * 2;
                if (k0     > q0) s[nt][0] = -1e30f;
                if (k0 + 1 > q0) s[nt][1] = -1e30f;
                if (k0     > q1) s[nt][2] = -1e30f;
                if (k0 + 1 > q1) s[nt][3] = -1e30f;
            }
        }

        // ---- streaming softmax (register, shfl) ----
        float mx0 = -1e30f, mx1 = -1e30f;
        #pragma unroll
        for (int nt = 0; nt < 8; nt++) {
            mx0 = fmaxf(mx0, fmaxf(s[nt][0], s[nt][1]));
            mx1 = fmaxf(mx1, fmaxf(s[nt][2], s[nt][3]));
        }
        mx0 = fmaxf(mx0, __shfl_xor_sync(0xffffffffu, mx0, 1));
        mx0 = fmaxf(mx0, __shfl_xor_sync(0xffffffffu, mx0, 2));
        mx1 = fmaxf(mx1, __shfl_xor_sync(0xffffffffu, mx1, 1));
        mx1 = fmaxf(mx1, __shfl_xor_sync(0xffffffffu, mx1, 2));
        float mn0 = fmaxf(m0, mx0), mn1 = fmaxf(m1, mx1);
        float a0 = __expf(m0 - mn0), a1 = __expf(m1 - mn1);
        m0 = mn0; m1 = mn1;

        float rs0 = 0.f, rs1 = 0.f;
        #pragma unroll
        for (int nt = 0; nt < 8; nt++) {
            s[nt][0] = __expf(s[nt][0] - mn0);
            s[nt][1] = __expf(s[nt][1] - mn0);
            s[nt][2] = __expf(s[nt][2] - mn1);
            s[nt][3] = __expf(s[nt][3] - mn1);
            rs0 += s[nt][0] + s[nt][1];
            rs1 += s[nt][2] + s[nt][3];
        }
        rs0 += __shfl_xor_sync(0xffffffffu, rs0, 1);
        rs0 += __shfl_xor_sync(0xffffffffu, rs0, 2);
        rs1 += __shfl_xor_sync(0xffffffffu, rs1, 1);
        rs1 += __shfl_xor_sync(0xffffffffu, rs1, 2);
        l0 = l0 * a0 + rs0;
        l1 = l1 * a1 + rs1;

        #pragma unroll
        for (int dt = 0; dt < 8; dt++) {
            o[dt][0] *= a0; o[dt][1] *= a0;
            o[dt][2] *= a1; o[dt][3] *= a1;
        }

        // ---- P -> A fragments (hi/lo) straight from accumulators ----
        uint32_t ph[4][4], pl[4][4];
        #pragma unroll
        for (int j = 0; j < 4; j++) {
            #pragma unroll
            for (int half = 0; half < 2; half++) {
                float p0 = s[2*j + half][0], p1 = s[2*j + half][1];
                float p2 = s[2*j + half][2], p3 = s[2*j + half][3];
                float h0 = __bfloat162float(__float2bfloat16(p0));
                float h1 = __bfloat162float(__float2bfloat16(p1));
                float h2 = __bfloat162float(__float2bfloat16(p2));
                float h3 = __bfloat162float(__float2bfloat16(p3));
                PACK_BF2(ph[j][0 + 2*half], p0, p1);
                PACK_BF2(ph[j][1 + 2*half], p2, p3);
                PACK_BF2(pl[j][0 + 2*half], p0 - h0, p1 - h1);
                PACK_BF2(pl[j][1 + 2*half], p2 - h2, p3 - h3);
            }
        }
        // fragment reg order: a0=(gr,2tig k-lo), a1=(gr+8,k-lo), a2=(gr,k-hi), a3=(gr+8,k-hi)
        // half=0 gives a0,a1 ; half=1 gives a2,a3 -> indices [0],[1],[2],[3] as packed above

        // ---- O += P V (bf16x3) ----
        #pragma unroll
        for (int kf = 0; kf < 4; kf++) {
            uint32_t vh[4][4], vl[4][4];
            int ch = kf * 2 + bcc;
            #pragma unroll
            for (int np = 0; np < 4; np++) {
                int row = brn + np * 16;
                uint32_t off = (uint32_t)(row * 128 + ((ch ^ (row & 7)) << 4));
                LDSM_X4(vh[np][0], vh[np][1], vh[np][2], vh[np][3], ks + 16384 + off);
                LDSM_X4(vl[np][0], vl[np][1], vl[np][2], vl[np][3], ks + 24576 + off);
            }
            #pragma unroll
            for (int dt = 0; dt < 8; dt++) {
                uint32_t b0h = vh[dt >> 1][(dt & 1) * 2];
                uint32_t b1h = vh[dt >> 1][(dt & 1) * 2 + 1];
                uint32_t b0l = vl[dt >> 1][(dt & 1) * 2];
                uint32_t b1l = vl[dt >> 1][(dt & 1) * 2 + 1];
                MMA_BF16(o[dt], ph[kf], b0h, b1h);
                MMA_BF16(o[dt], pl[kf], b0h, b1h);
                MMA_BF16(o[dt], ph[kf], b0l, b1l);
            }
        }
        __syncthreads();
    }

    // ---- epilogue ----
    float il0 = 1.f / l0, il1 = 1.f / l1;
    int q0 = wq0 + (lane >> 2);
    size_t ob = ((size_t)(b * S_LEN)) * D_MODEL + h * HD;
    #pragma unroll
    for (int dt = 0; dt < 8; dt++) {
        int d = dt * 8 + (lane & 3) * 2;
        *(float2*)&g_O[ob + (size_t)q0 * D_MODEL + d] =
            make_float2(o[dt][0] * il0, o[dt][1] * il0);
        *(float2*)&g_O[ob + (size_t)(q0 + 8) * D_MODEL + d] =
            make_float2(o[dt][2] * il1, o[dt][3] * il1);
    }
}

// ======================= host launch =========================================
static void launch_gemm(const __nv_bfloat16* Ah, const __nv_bfloat16* Al,
                        const __nv_bfloat16* Bh, const __nv_bfloat16* Bl,
                        float* C, int M, int N, int K)
{
    size_t shm = STAGES * STAGE_B + 1024;
    cudaFuncSetAttribute(gemm_mma, cudaFuncAttributeMaxDynamicSharedMemorySize, (int)shm);
    gemm_mma<<<dim3(N / BN, M / BM), 256, shm>>>(Ah, Al, Bh, Bl, C, M, N, K);
}

extern "C" void kernel_launch(void* const* d_in, const int* in_sizes, int n_in,
                              void* d_out, int out_size)
{
    const float* x  = (const float*)d_in[0];
    const float* wq = (const float*)d_in[2];
    const float* wk = (const float*)d_in[3];
    const float* wv = (const float*)d_in[4];
    const float* wo = (const float*)d_in[5];
    float* out = (float*)d_out;

    float *qp, *kp, *vp, *op;
    __nv_bfloat16 *xh, *xl, *wh, *wl;
    cudaGetSymbolAddress((void**)&qp, g_Q);
    cudaGetSymbolAddress((void**)&kp, g_K);
    cudaGetSymbolAddress((void**)&vp, g_V);
    cudaGetSymbolAddress((void**)&op, g_O);
    cudaGetSymbolAddress((void**)&xh, g_xh);
    cudaGetSymbolAddress((void**)&xl, g_xl);
    cudaGetSymbolAddress((void**)&wh, g_wh);
    cudaGetSymbolAddress((void**)&wl, g_wl);

    int n4 = ROWS * D_MODEL / 4;
    split_kernel<<<(n4 + 255) / 256, 256>>>(x, xh, xl, n4);

    splitT_kernel<<<dim3(D_MODEL / 32, D_MODEL / 32), dim3(32, 8)>>>(wq, wh, wl, D_MODEL, D_MODEL);
    launch_gemm(xh, xl, wh, wl, qp, ROWS, D_MODEL, D_MODEL);
    splitT_kernel<<<dim3(KV_DIM / 32, D_MODEL / 32), dim3(32, 8)>>>(wk, wh, wl, D_MODEL, KV_DIM);
    launch_gemm(xh, xl, wh, wl, kp, ROWS, KV_DIM, D_MODEL);
    splitT_kernel<<<dim3(KV_DIM / 32, D_MODEL / 32), dim3(32, 8)>>>(wv, wh, wl, D_MODEL, KV_DIM);
    launch_gemm(xh, xl, wh, wl, vp, ROWS, KV_DIM, D_MODEL);

    // RoPE + bf16 hi/lo split precompute
    Freqs fr;
    for (int p = 0; p < 32; p++)
        fr.f[p] = (float)pow(10000.0, -(double)(2 * p) / 64.0);
    rope_split_q<<<(ROWS * NH * 32) / 256, 256>>>(fr);
    rope_split_k<<<(ROWS * NKV * 32) / 256, 256>>>(fr);
    vsplit_t<<<dim3(S_LEN / 32, HD / 32, BATCH * NKV), dim3(32, 8)>>>();

    // flash attention (tensor cores)
    size_t fshm = 3 * 32768 + 1024;   // Q(32K) + 2 stages(64K) + align
    cudaFuncSetAttribute(flash_mma, cudaFuncAttributeMaxDynamicSharedMemorySize, (int)fshm);
    flash_mma<<<dim3(S_LEN / 128, NH, BATCH), 256, fshm>>>();

    // out = O @ wo
    split_kernel<<<(n4 + 255) / 256, 256>>>(op, xh, xl, n4);
    splitT_kernel<<<dim3(D_MODEL / 32, D_MODEL / 32), dim3(32, 8)>>>(wo, wh, wl, D_MODEL, D_MODEL);
    launch_gemm(xh, xl, wh, wl, out, ROWS, D_MODEL, D_MODEL);
}

// round 5
// speedup vs baseline: 3.5511x; 1.0897x over previous
#include <cuda_runtime.h>
#include <cuda_bf16.h>
#include <math.h>
#include <stdint.h>

#define S_LEN   2048
#define BATCH   2
#define D_MODEL 2048
#define KV_DIM  512
#define NH      32
#define NKV     8
#define HD      64
#define ROWS    (BATCH*S_LEN)   // 4096

// ---------------- scratch (device globals; no allocation allowed) ----------
__device__ float g_V[ROWS*KV_DIM];
__device__ __nv_bfloat16 g_xh[ROWS*D_MODEL];       // x split hi (later: attn out hi)
__device__ __nv_bfloat16 g_xl[ROWS*D_MODEL];
__device__ __nv_bfloat16 g_whq[D_MODEL*D_MODEL];   // wq^T hi/lo
__device__ __nv_bfloat16 g_wlq[D_MODEL*D_MODEL];
__device__ __nv_bfloat16 g_whkv[2*KV_DIM*D_MODEL]; // [wk^T ; wv^T] hi/lo
__device__ __nv_bfloat16 g_wlkv[2*KV_DIM*D_MODEL];
__device__ __nv_bfloat16 g_who[D_MODEL*D_MODEL];   // wo^T hi/lo
__device__ __nv_bfloat16 g_wlo[D_MODEL*D_MODEL];
__device__ __nv_bfloat16 g_Qh[ROWS*D_MODEL];       // RoPE'd, 0.125-scaled
__device__ __nv_bfloat16 g_Ql[ROWS*D_MODEL];
__device__ __nv_bfloat16 g_Kh[ROWS*KV_DIM];
__device__ __nv_bfloat16 g_Kl[ROWS*KV_DIM];
__device__ __nv_bfloat16 g_Vth[BATCH*NKV*HD*S_LEN]; // [b][kvh][d][s]
__device__ __nv_bfloat16 g_Vtl[BATCH*NKV*HD*S_LEN];
__device__ float g_cos[S_LEN*32];
__device__ float g_sin[S_LEN*32];

// ======================= base-ISA PTX helpers ===============================
__device__ __forceinline__ uint32_t smem_u32(const void* p) {
    uint32_t a;
    asm("{ .reg .u64 t; cvta.to.shared.u64 t, %1; cvt.u32.u64 %0, t; }"
        : "=r"(a) : "l"(p));
    return a;
}
__device__ __forceinline__ void cpa16(uint32_t saddr, const void* g) {
    asm volatile("cp.async.cg.shared.global [%0], [%1], 16;" :: "r"(saddr), "l"(g));
}
#define CP_COMMIT() asm volatile("cp.async.commit_group;" ::: "memory")
#define CP_WAIT(n)  asm volatile("cp.async.wait_group %0;" :: "n"(n) : "memory")

#define LDSM_X4(r0, r1, r2, r3, a) \
    asm volatile("ldmatrix.sync.aligned.m8n8.x4.shared.b16 {%0,%1,%2,%3}, [%4];" \
        : "=r"(r0), "=r"(r1), "=r"(r2), "=r"(r3) : "r"(a))

#define MMA_BF16(d, a, b0, b1) \
    asm volatile("mma.sync.aligned.m16n8k16.row.col.f32.bf16.bf16.f32 " \
        "{%0,%1,%2,%3}, {%4,%5,%6,%7}, {%8,%9}, {%0,%1,%2,%3};" \
        : "+f"((d)[0]), "+f"((d)[1]), "+f"((d)[2]), "+f"((d)[3]) \
        : "r"((a)[0]), "r"((a)[1]), "r"((a)[2]), "r"((a)[3]), "r"(b0), "r"(b1))

#define PACK_BF2(d, lo, hi) \
    asm("cvt.rn.bf16x2.f32 %0, %1, %2;" : "=r"(d) : "f"(hi), "f"(lo))

// ======================= small precompute kernels ===========================
struct Freqs { float f[32]; };

__global__ void rope_table(Freqs fr)
{
    int i = blockIdx.x * blockDim.x + threadIdx.x;   // S_LEN*32
    int s = i >> 5, p = i & 31;
    float ang = (float)s * fr.f[p];
    float c, sn;
    sincosf(ang, &sn, &c);
    g_cos[i] = c;
    g_sin[i] = sn;
}

__global__ void split_kernel(const float* __restrict__ a,
                             __nv_bfloat16* __restrict__ hi,
                             __nv_bfloat16* __restrict__ lo, int n4)
{
    int i = blockIdx.x * blockDim.x + threadIdx.x;
    if (i >= n4) return;
    float4 v = ((const float4*)a)[i];
    __nv_bfloat16 h0 = __float2bfloat16(v.x), h1 = __float2bfloat16(v.y);
    __nv_bfloat16 h2 = __float2bfloat16(v.z), h3 = __float2bfloat16(v.w);
    __nv_bfloat16 l0 = __float2bfloat16(v.x - __bfloat162float(h0));
    __nv_bfloat16 l1 = __float2bfloat16(v.y - __bfloat162float(h1));
    __nv_bfloat16 l2 = __float2bfloat16(v.z - __bfloat162float(h2));
    __nv_bfloat16 l3 = __float2bfloat16(v.w - __bfloat162float(h3));
    ((__nv_bfloat162*)hi)[2*i]   = __nv_bfloat162(h0, h1);
    ((__nv_bfloat162*)hi)[2*i+1] = __nv_bfloat162(h2, h3);
    ((__nv_bfloat162*)lo)[2*i]   = __nv_bfloat162(l0, l1);
    ((__nv_bfloat162*)lo)[2*i+1] = __nv_bfloat162(l2, l3);
}

__global__ void splitT_kernel(const float* __restrict__ w,
                              __nv_bfloat16* __restrict__ th,
                              __nv_bfloat16* __restrict__ tl, int Kd, int Nd)
{
    __shared__ float t[32][33];
    int n0 = blockIdx.x * 32, k0 = blockIdx.y * 32;
    for (int r = threadIdx.y; r < 32; r += 8)
        t[r][threadIdx.x] = w[(size_t)(k0 + r) * Nd + n0 + threadIdx.x];
    __syncthreads();
    for (int r = threadIdx.y; r < 32; r += 8) {
        float v = t[threadIdx.x][r];
        __nv_bfloat16 h = __float2bfloat16(v);
        __nv_bfloat16 l = __float2bfloat16(v - __bfloat162float(h));
        th[(size_t)(n0 + r) * Kd + k0 + threadIdx.x] = h;
        tl[(size_t)(n0 + r) * Kd + k0 + threadIdx.x] = l;
    }
}

// V[b*S+s][kvh*64+d] fp32 -> Vt[(b*NKV+kvh)*64+d][s] bf16 hi/lo
__global__ void vsplit_t()
{
    __shared__ float t[32][33];
    int bz = blockIdx.z;
    int d0 = blockIdx.y * 32;
    int s0 = blockIdx.x * 32;
    int b = bz >> 3, kvh = bz & 7;
    int tx = threadIdx.x, ty = threadIdx.y;
    for (int i = 0; i < 4; i++) {
        int r = ty + i * 8;
        t[r][tx] = g_V[(size_t)(b * S_LEN + s0 + r) * KV_DIM + kvh * HD + d0 + tx];
    }
    __syncthreads();
    for (int i = 0; i < 4; i++) {
        int rr = ty + i * 8;
        float v = t[tx][rr];
        __nv_bfloat16 h = __float2bfloat16(v);
        __nv_bfloat16 l = __float2bfloat16(v - __bfloat162float(h));
        size_t o = (size_t)(bz * HD + d0 + rr) * S_LEN + s0 + tx;
        g_Vth[o] = h;
        g_Vtl[o] = l;
    }
}

// ======================= mma.sync bf16x3 GEMM ===============================
// EPI 0: plain fp32 -> C.   EPI 1: rope+0.125+split -> g_Qh/g_Ql.
// EPI 3: cols<512 rope+split -> g_Kh/g_Kl; cols>=512 fp32 -> g_V.
#define BM 128
#define BN 128
#define BK 32
#define STAGES 3
#define TILE_B  (BM*BK*2)
#define STAGE_B (4*TILE_B)

template<int EPI>
__global__ __launch_bounds__(256, 2) void gemm_mma(
    const __nv_bfloat16* __restrict__ Ah, const __nv_bfloat16* __restrict__ Al,
    const __nv_bfloat16* __restrict__ Bh, const __nv_bfloat16* __restrict__ Bl,
    float* __restrict__ C, int M, int N, int K)
{
    extern __shared__ char smem_raw[];
    const int tid  = threadIdx.x;
    const int wid  = tid >> 5;
    const int lane = tid & 31;
    const int m0 = blockIdx.y * BM, n0 = blockIdx.x * BN;
    const int wm = (wid >> 2) * 64;
    const int wn = (wid & 3) * 32;
    const int nk = K / BK;

    uint32_t raw = smem_u32(smem_raw);
    uint32_t st  = (raw + 1023u) & ~1023u;

    const __nv_bfloat16* gA_h = Ah + (size_t)m0 * K;
    const __nv_bfloat16* gA_l = Al + (size_t)m0 * K;
    const __nv_bfloat16* gB_h = Bh + (size_t)n0 * K;
    const __nv_bfloat16* gB_l = Bl + (size_t)n0 * K;

    const int ci0 = tid, ci1 = tid + 256;
    const int r0c = ci0 >> 2, c0c = ci0 & 3;
    const int r1c = ci1 >> 2, c1c = ci1 & 3;
    const uint32_t so0 = r0c * 64 + ((c0c ^ ((r0c >> 1) & 3)) << 4);
    const uint32_t so1 = r1c * 64 + ((c1c ^ ((r1c >> 1) & 3)) << 4);
    const size_t go0 = (size_t)r0c * K + c0c * 8;
    const size_t go1 = (size_t)r1c * K + c1c * 8;

    auto load_stage = [&](int s, int j) {
        uint32_t sb = st + s * STAGE_B;
        size_t kk = (size_t)j * BK;
        cpa16(sb + so0,              gA_h + kk + go0);
        cpa16(sb + so1,              gA_h + kk + go1);
        cpa16(sb + TILE_B + so0,     gA_l + kk + go0);
        cpa16(sb + TILE_B + so1,     gA_l + kk + go1);
        cpa16(sb + 2*TILE_B + so0,   gB_h + kk + go0);
        cpa16(sb + 2*TILE_B + so1,   gB_h + kk + go1);
        cpa16(sb + 3*TILE_B + so0,   gB_l + kk + go0);
        cpa16(sb + 3*TILE_B + so1,   gB_l + kk + go1);
    };

    float acc[4][4][4];
    #pragma unroll
    for (int i = 0; i < 4; i++)
        #pragma unroll
        for (int j = 0; j < 4; j++)
            #pragma unroll
            for (int k = 0; k < 4; k++) acc[i][j][k] = 0.f;

    const int arow = wm + (lane & 15);
    const int acol = (lane >> 4);
    const int brow = wn + (lane & 7) + ((lane >> 4) & 1) * 8;
    const int bcol = (lane >> 3) & 1;

    #pragma unroll
    for (int s = 0; s < STAGES - 1; s++) {
        if (s < nk) load_stage(s, s);
        CP_COMMIT();
    }

    for (int i = 0; i < nk; i++) {
        int pf = i + STAGES - 1;
        if (pf < nk) load_stage(pf % STAGES, pf);
        CP_COMMIT();
        CP_WAIT(STAGES - 2);
        __syncthreads();

        uint32_t sb = st + (i % STAGES) * STAGE_B;
        #pragma unroll
        for (int ks = 0; ks < 2; ks++) {
            uint32_t ah[4][4], al[4][4], bh[2][4], bl[2][4];
            int ca = 2 * ks + acol;
            #pragma unroll
            for (int mt = 0; mt < 4; mt++) {
                int row = arow + mt * 16;
                uint32_t ad = sb + row * 64 + ((ca ^ ((row >> 1) & 3)) << 4);
                LDSM_X4(ah[mt][0], ah[mt][1], ah[mt][2], ah[mt][3], ad);
                LDSM_X4(al[mt][0], al[mt][1], al[mt][2], al[mt][3], ad + TILE_B);
            }
            int cb = 2 * ks + bcol;
            #pragma unroll
            for (int nt = 0; nt < 2; nt++) {
                int row = brow + nt * 16;
                uint32_t bd = sb + 2*TILE_B + row * 64 + ((cb ^ ((row >> 1) & 3)) << 4);
                LDSM_X4(bh[nt][0], bh[nt][1], bh[nt][2], bh[nt][3], bd);
                LDSM_X4(bl[nt][0], bl[nt][1], bl[nt][2], bl[nt][3], bd + TILE_B);
            }
            #pragma unroll
            for (int mt = 0; mt < 4; mt++)
                #pragma unroll
                for (int nti = 0; nti < 4; nti++) {
                    uint32_t b0h = bh[nti >> 1][(nti & 1) * 2];
                    uint32_t b1h = bh[nti >> 1][(nti & 1) * 2 + 1];
                    uint32_t b0l = bl[nti >> 1][(nti & 1) * 2];
                    uint32_t b1l = bl[nti >> 1][(nti & 1) * 2 + 1];
                    MMA_BF16(acc[mt][nti], ah[mt], b0h, b1h);
                    MMA_BF16(acc[mt][nti], ah[mt], b0l, b1l);
                    MMA_BF16(acc[mt][nti], al[mt], b0h, b1h);
                }
        }
        __syncthreads();
    }

    // ---- epilogue ----
    if constexpr (EPI == 0) {
        #pragma unroll
        for (int mt = 0; mt < 4; mt++)
            #pragma unroll
            for (int nti = 0; nti < 4; nti++) {
                int gm = m0 + wm + mt * 16 + (lane >> 2);
                int gn = n0 + wn + nti * 8 + (lane & 3) * 2;
                *(float2*)&C[(size_t)gm * N + gn] =
                    make_float2(acc[mt][nti][0], acc[mt][nti][1]);
                *(float2*)&C[(size_t)(gm + 8) * N + gn] =
                    make_float2(acc[mt][nti][2], acc[mt][nti][3]);
            }
    } else {
        const bool isV = (EPI == 3) && (n0 >= KV_DIM);
        #pragma unroll
        for (int mt = 0; mt < 4; mt++)
            #pragma unroll
            for (int nti = 0; nti < 4; nti++) {
                int gm = m0 + wm + mt * 16 + (lane >> 2);
                int gn = n0 + wn + nti * 8 + (lane & 3) * 2;
                #pragma unroll
                for (int rr = 0; rr < 2; rr++) {
                    int row = gm + rr * 8;
                    float v0 = acc[mt][nti][2*rr], v1 = acc[mt][nti][2*rr + 1];
                    if (isV) {
                        *(float2*)&g_V[(size_t)row * KV_DIM + (gn - KV_DIM)] =
                            make_float2(v0, v1);
                    } else {
                        int s = row & (S_LEN - 1);
                        int p = (gn & 63) >> 1;
                        float c = g_cos[(s << 5) + p], sn = g_sin[(s << 5) + p];
                        float xr = v0 * c - v1 * sn;
                        float xi = v0 * sn + v1 * c;
                        if (EPI == 1) { xr *= 0.125f; xi *= 0.125f; }
                        __nv_bfloat16 hr = __float2bfloat16(xr);
                        __nv_bfloat16 hi2 = __float2bfloat16(xi);
                        __nv_bfloat16 lr = __float2bfloat16(xr - __bfloat162float(hr));
                        __nv_bfloat16 li = __float2bfloat16(xi - __bfloat162float(hi2));
                        if (EPI == 1) {
                            *(__nv_bfloat162*)&g_Qh[(size_t)row * D_MODEL + gn] =
                                __nv_bfloat162(hr, hi2);
                            *(__nv_bfloat162*)&g_Ql[(size_t)row * D_MODEL + gn] =
                                __nv_bfloat162(lr, li);
                        } else {
                            *(__nv_bfloat162*)&g_Kh[(size_t)row * KV_DIM + gn] =
                                __nv_bfloat162(hr, hi2);
                            *(__nv_bfloat162*)&g_Kl[(size_t)row * KV_DIM + gn] =
                                __nv_bfloat162(lr, li);
                        }
                    }
                }
            }
    }
}

// ======================= flash attention, mma.sync bf16x3 ===================
#define SQH 0
#define SQL 16384
#define SST 32768
#define FSTG 32768   // Kh 0 | Kl 8K | Vh 16K | Vl 24K

__global__ __launch_bounds__(256, 1) void flash_mma()
{
    extern __shared__ char smem_raw[];
    uint32_t raw = smem_u32(smem_raw);
    uint32_t sb = (raw + 1023u) & ~1023u;

    const int tid = threadIdx.x, lane = tid & 31, w = tid >> 5;
    const int qt = gridDim.x - 1 - blockIdx.x;
    const int h = blockIdx.y, b = blockIdx.z;
    const int kvh = h >> 2;
    const int wq0 = qt * 128 + w * 16;

    {
        const size_t qg = ((size_t)(b * S_LEN + qt * 128)) * D_MODEL + h * HD;
        #pragma unroll
        for (int it = 0; it < 4; it++) {
            int c = tid + it * 256;
            int r = c >> 3, ch = c & 7;
            uint32_t so = (uint32_t)(r * 128 + ((ch ^ (r & 7)) << 4));
            size_t go = qg + (size_t)r * D_MODEL + ch * 8;
            cpa16(sb + SQH + so, g_Qh + go);
            cpa16(sb + SQL + so, g_Ql + go);
        }
    }
    CP_COMMIT();

    const int ldr = tid >> 3, ldc = tid & 7;
    const uint32_t lso0 = (uint32_t)(ldr * 128 + ((ldc ^ (ldr & 7)) << 4));
    const uint32_t lso1 = (uint32_t)((ldr + 32) * 128 + ((ldc ^ ((ldr + 32) & 7)) << 4));

    auto load_kv = [&](int stage, int kb) {
        uint32_t ss = sb + SST + stage * FSTG;
        size_t kg = ((size_t)(b * S_LEN + kb * 64)) * KV_DIM + kvh * HD;
        size_t vg = ((size_t)((b * NKV + kvh) * HD)) * S_LEN + (size_t)kb * 64;
        size_t kg0 = kg + (size_t)ldr * KV_DIM + ldc * 8;
        size_t kg1 = kg + (size_t)(ldr + 32) * KV_DIM + ldc * 8;
        size_t vg0 = vg + (size_t)ldr * S_LEN + ldc * 8;
        size_t vg1 = vg + (size_t)(ldr + 32) * S_LEN + ldc * 8;
        cpa16(ss + lso0,         g_Kh + kg0);
        cpa16(ss + lso1,         g_Kh + kg1);
        cpa16(ss + 8192 + lso0,  g_Kl + kg0);
        cpa16(ss + 8192 + lso1,  g_Kl + kg1);
        cpa16(ss + 16384 + lso0, g_Vth + vg0);
        cpa16(ss + 16384 + lso1, g_Vth + vg1);
        cpa16(ss + 24576 + lso0, g_Vtl + vg0);
        cpa16(ss + 24576 + lso1, g_Vtl + vg1);
        CP_COMMIT();
    };

    load_kv(0, 0);
    CP_WAIT(1);
    __syncthreads();

    uint32_t qh[4][4], ql[4][4];
    {
        int row = w * 16 + (lane & 15);
        int rb = row * 128;
        #pragma unroll
        for (int kf = 0; kf < 4; kf++) {
            int ch = kf * 2 + (lane >> 4);
            uint32_t off = (uint32_t)(rb + ((ch ^ (row & 7)) << 4));
            LDSM_X4(qh[kf][0], qh[kf][1], qh[kf][2], qh[kf][3], sb + SQH + off);
            LDSM_X4(ql[kf][0], ql[kf][1], ql[kf][2], ql[kf][3], sb + SQL + off);
        }
    }

    float o[8][4];
    #pragma unroll
    for (int i = 0; i < 8; i++)
        #pragma unroll
        for (int j = 0; j < 4; j++) o[i][j] = 0.f;
    float m0 = -1e30f, m1 = -1e30f, l0 = 0.f, l1 = 0.f;

    const int brn = (lane & 7) + ((lane >> 4) & 1) * 8;
    const int bcc = (lane >> 3) & 1;
    const int nkb = 2 * qt + 2;

    for (int kb = 0; kb < nkb; kb++) {
        if (kb + 1 < nkb) {
            load_kv((kb + 1) & 1, kb + 1);
            CP_WAIT(1);
        } else {
            CP_WAIT(0);
        }
        __syncthreads();

        uint32_t ks = sb + SST + (kb & 1) * FSTG;

        float s[8][4];
        #pragma unroll
        for (int i = 0; i < 8; i++)
            #pragma unroll
            for (int j = 0; j < 4; j++) s[i][j] = 0.f;

        #pragma unroll
        for (int kf = 0; kf < 4; kf++) {
            uint32_t bh[4][4], bl[4][4];
            int ch = kf * 2 + bcc;
            #pragma unroll
            for (int np = 0; np < 4; np++) {
                int row = brn + np * 16;
                uint32_t off = (uint32_t)(row * 128 + ((ch ^ (row & 7)) << 4));
                LDSM_X4(bh[np][0], bh[np][1], bh[np][2], bh[np][3], ks + off);
                LDSM_X4(bl[np][0], bl[np][1], bl[np][2], bl[np][3], ks + 8192 + off);
            }
            #pragma unroll
            for (int nt = 0; nt < 8; nt++) {
                uint32_t b0h = bh[nt >> 1][(nt & 1) * 2];
                uint32_t b1h = bh[nt >> 1][(nt & 1) * 2 + 1];
                uint32_t b0l = bl[nt >> 1][(nt & 1) * 2];
                uint32_t b1l = bl[nt >> 1][(nt & 1) * 2 + 1];
                MMA_BF16(s[nt], qh[kf], b0h, b1h);
                MMA_BF16(s[nt], qh[kf], b0l, b1l);
                MMA_BF16(s[nt], ql[kf], b0h, b1h);
            }
        }

        int kbase = kb * 64;
        if (kbase + 63 > wq0) {
            int q0 = wq0 + (lane >> 2);
            int q1 = q0 + 8;
            #pragma unroll
            for (int nt = 0; nt < 8; nt++) {
                int k0 = kbase + nt * 8 + (lane & 3) * 2;
                if (k0     > q0) s[nt][0] = -1e30f;
                if (k0 + 1 > q0) s[nt][1] = -1e30f;
                if (k0     > q1) s[nt][2] = -1e30f;
                if (k0 + 1 > q1) s[nt][3] = -1e30f;
            }
        }

        float mx0 = -1e30f, mx1 = -1e30f;
        #pragma unroll
        for (int nt = 0; nt < 8; nt++) {
            mx0 = fmaxf(mx0, fmaxf(s[nt][0], s[nt][1]));
            mx1 = fmaxf(mx1, fmaxf(s[nt][2], s[nt][3]));
        }
        mx0 = fmaxf(mx0, __shfl_xor_sync(0xffffffffu, mx0, 1));
        mx0 = fmaxf(mx0, __shfl_xor_sync(0xffffffffu, mx0, 2));
        mx1 = fmaxf(mx1, __shfl_xor_sync(0xffffffffu, mx1, 1));
        mx1 = fmaxf(mx1, __shfl_xor_sync(0xffffffffu, mx1, 2));
        float mn0 = fmaxf(m0, mx0), mn1 = fmaxf(m1, mx1);
        float a0 = __expf(m0 - mn0), a1 = __expf(m1 - mn1);
        m0 = mn0; m1 = mn1;

        float rs0 = 0.f, rs1 = 0.f;
        #pragma unroll
        for (int nt = 0; nt < 8; nt++) {
            s[nt][0] = __expf(s[nt][0] - mn0);
            s[nt][1] = __expf(s[nt][1] - mn0);
            s[nt][2] = __expf(s[nt][2] - mn1);
            s[nt][3] = __expf(s[nt][3] - mn1);
            rs0 += s[nt][0] + s[nt][1];
            rs1 += s[nt][2] + s[nt][3];
        }
        rs0 += __shfl_xor_sync(0xffffffffu, rs0, 1);
        rs0 += __shfl_xor_sync(0xffffffffu, rs0, 2);
        rs1 += __shfl_xor_sync(0xffffffffu, rs1, 1);
        rs1 += __shfl_xor_sync(0xffffffffu, rs1, 2);
        l0 = l0 * a0 + rs0;
        l1 = l1 * a1 + rs1;

        #pragma unroll
        for (int dt = 0; dt < 8; dt++) {
            o[dt][0] *= a0; o[dt][1] *= a0;
            o[dt][2] *= a1; o[dt][3] *= a1;
        }

        uint32_t ph[4][4], pl[4][4];
        #pragma unroll
        for (int j = 0; j < 4; j++) {
            #pragma unroll
            for (int half = 0; half < 2; half++) {
                float p0 = s[2*j + half][0], p1 = s[2*j + half][1];
                float p2 = s[2*j + half][2], p3 = s[2*j + half][3];
                float h0 = __bfloat162float(__float2bfloat16(p0));
                float h1 = __bfloat162float(__float2bfloat16(p1));
                float h2 = __bfloat162float(__float2bfloat16(p2));
                float h3 = __bfloat162float(__float2bfloat16(p3));
                PACK_BF2(ph[j][0 + 2*half], p0, p1);
                PACK_BF2(ph[j][1 + 2*half], p2, p3);
                PACK_BF2(pl[j][0 + 2*half], p0 - h0, p1 - h1);
                PACK_BF2(pl[j][1 + 2*half], p2 - h2, p3 - h3);
            }
        }

        #pragma unroll
        for (int kf = 0; kf < 4; kf++) {
            uint32_t vh[4][4], vl[4][4];
            int ch = kf * 2 + bcc;
            #pragma unroll
            for (int np = 0; np < 4; np++) {
                int row = brn + np * 16;
                uint32_t off = (uint32_t)(row * 128 + ((ch ^ (row & 7)) << 4));
                LDSM_X4(vh[np][0], vh[np][1], vh[np][2], vh[np][3], ks + 16384 + off);
                LDSM_X4(vl[np][0], vl[np][1], vl[np][2], vl[np][3], ks + 24576 + off);
            }
            #pragma unroll
            for (int dt = 0; dt < 8; dt++) {
                uint32_t b0h = vh[dt >> 1][(dt & 1) * 2];
                uint32_t b1h = vh[dt >> 1][(dt & 1) * 2 + 1];
                uint32_t b0l = vl[dt >> 1][(dt & 1) * 2];
                uint32_t b1l = vl[dt >> 1][(dt & 1) * 2 + 1];
                MMA_BF16(o[dt], ph[kf], b0h, b1h);
                MMA_BF16(o[dt], pl[kf], b0h, b1h);
                MMA_BF16(o[dt], ph[kf], b0l, b1l);
            }
        }
        __syncthreads();
    }

    // ---- epilogue: write bf16 hi/lo split directly (A operand of out-proj) ----
    float il0 = 1.f / l0, il1 = 1.f / l1;
    int q0 = wq0 + (lane >> 2);
    size_t ob = ((size_t)(b * S_LEN)) * D_MODEL + h * HD;
    #pragma unroll
    for (int dt = 0; dt < 8; dt++) {
        int d = dt * 8 + (lane & 3) * 2;
        #pragma unroll
        for (int rr = 0; rr < 2; rr++) {
            float v0 = o[dt][2*rr]     * (rr ? il1 : il0);
            float v1 = o[dt][2*rr + 1] * (rr ? il1 : il0);
            __nv_bfloat16 h0 = __float2bfloat16(v0);
            __nv_bfloat16 h1 = __float2bfloat16(v1);
            __nv_bfloat16 l0b = __float2bfloat16(v0 - __bfloat162float(h0));
            __nv_bfloat16 l1b = __float2bfloat16(v1 - __bfloat162float(h1));
            size_t off = ob + (size_t)(q0 + rr * 8) * D_MODEL + d;
            *(__nv_bfloat162*)&g_xh[off] = __nv_bfloat162(h0, h1);
            *(__nv_bfloat162*)&g_xl[off] = __nv_bfloat162(l0b, l1b);
        }
    }
}

// ======================= host launch =========================================
extern "C" void kernel_launch(void* const* d_in, const int* in_sizes, int n_in,
                              void* d_out, int out_size)
{
    const float* x  = (const float*)d_in[0];
    const float* wq = (const float*)d_in[2];
    const float* wk = (const float*)d_in[3];
    const float* wv = (const float*)d_in[4];
    const float* wo = (const float*)d_in[5];
    float* out = (float*)d_out;

    __nv_bfloat16 *xh, *xl, *whq, *wlq, *whkv, *wlkv, *who, *wlo;
    cudaGetSymbolAddress((void**)&xh, g_xh);
    cudaGetSymbolAddress((void**)&xl, g_xl);
    cudaGetSymbolAddress((void**)&whq, g_whq);
    cudaGetSymbolAddress((void**)&wlq, g_wlq);
    cudaGetSymbolAddress((void**)&whkv, g_whkv);
    cudaGetSymbolAddress((void**)&wlkv, g_wlkv);
    cudaGetSymbolAddress((void**)&who, g_who);
    cudaGetSymbolAddress((void**)&wlo, g_wlo);

    // RoPE cos/sin table (accurate sincosf, once)
    Freqs fr;
    for (int p = 0; p < 32; p++)
        fr.f[p] = (float)pow(10000.0, -(double)(2 * p) / 64.0);
    rope_table<<<(S_LEN * 32) / 256, 256>>>(fr);

    // operand conversions (all upfront)
    int n4 = ROWS * D_MODEL / 4;
    split_kernel<<<(n4 + 255) / 256, 256>>>(x, xh, xl, n4);
    splitT_kernel<<<dim3(D_MODEL / 32, D_MODEL / 32), dim3(32, 8)>>>(wq, whq, wlq, D_MODEL, D_MODEL);
    splitT_kernel<<<dim3(KV_DIM / 32, D_MODEL / 32), dim3(32, 8)>>>(wk, whkv, wlkv, D_MODEL, KV_DIM);
    splitT_kernel<<<dim3(KV_DIM / 32, D_MODEL / 32), dim3(32, 8)>>>(
        wv, whkv + (size_t)KV_DIM * D_MODEL, wlkv + (size_t)KV_DIM * D_MODEL, D_MODEL, KV_DIM);
    splitT_kernel<<<dim3(D_MODEL / 32, D_MODEL / 32), dim3(32, 8)>>>(wo, who, wlo, D_MODEL, D_MODEL);

    size_t shm = STAGES * STAGE_B + 1024;
    cudaFuncSetAttribute(gemm_mma<0>, cudaFuncAttributeMaxDynamicSharedMemorySize, (int)shm);
    cudaFuncSetAttribute(gemm_mma<1>, cudaFuncAttributeMaxDynamicSharedMemorySize, (int)shm);
    cudaFuncSetAttribute(gemm_mma<3>, cudaFuncAttributeMaxDynamicSharedMemorySize, (int)shm);

    // Q = rope(x@wq)*0.125 -> bf16 split (fused epilogue)
    gemm_mma<1><<<dim3(D_MODEL / BN, ROWS / BM), 256, shm>>>(
        xh, xl, whq, wlq, nullptr, ROWS, D_MODEL, D_MODEL);
    // [K|V] = x@[wk|wv]; K gets rope+split, V raw fp32 (fused epilogue)
    gemm_mma<3><<<dim3(2 * KV_DIM / BN, ROWS / BM), 256, shm>>>(
        xh, xl, whkv, wlkv, nullptr, ROWS, 2 * KV_DIM, D_MODEL);
    // V transpose + split
    vsplit_t<<<dim3(S_LEN / 32, HD / 32, BATCH * NKV), dim3(32, 8)>>>();

    // flash attention -> writes bf16 split into xh/xl
    size_t fshm = 3 * 32768 + 1024;
    cudaFuncSetAttribute(flash_mma, cudaFuncAttributeMaxDynamicSharedMemorySize, (int)fshm);
    flash_mma<<<dim3(S_LEN / 128, NH, BATCH), 256, fshm>>>();

    // out = attn @ wo
    gemm_mma<0><<<dim3(D_MODEL / BN, ROWS / BM), 256, shm>>>(
        xh, xl, who, wlo, out, ROWS, D_MODEL, D_MODEL);
}